// round 1
// baseline (speedup 1.0000x reference)
#include <cuda_runtime.h>
#include <cstdint>

#define S  4096
#define H  256
#define NH 6
#define TH 768           // 3*H
#define LN_EPS 1e-5f

// ---------------- scratch (static device globals: allocation-free) ----------
__device__ float g_x[S * H];                       // embedded tokens
__device__ float g_q[NH * S * H];
__device__ float g_k[NH * S * H];
__device__ float g_v[NH * S * H];
__device__ float g_att[(size_t)NH * S * S];        // 402 MB score/prob buffer
__device__ float g_o[S * NH * H];                  // concat head outputs [s, h*H+e]
__device__ float g_pre[S * H];                     // x + attn (pre-LN)
__device__ float g_y[S * H];                       // LN output
__device__ float g_gi[S * TH];                     // precomputed input gates

// ---------------- small helpers ---------------------------------------------
__device__ __forceinline__ uint32_t smem_u32(const void* p) {
    return (uint32_t)__cvta_generic_to_shared(p);
}
__device__ __forceinline__ void st_cluster_f32(uint32_t saddr, uint32_t rank, float v) {
    uint32_t r;
    asm volatile("mapa.shared::cluster.u32 %0, %1, %2;" : "=r"(r) : "r"(saddr), "r"(rank));
    asm volatile("st.shared::cluster.f32 [%0], %1;" :: "r"(r), "f"(v) : "memory");
}
__device__ __forceinline__ void cluster_sync_() {
    asm volatile("barrier.cluster.arrive.aligned;" ::: "memory");
    asm volatile("barrier.cluster.wait.aligned;"   ::: "memory");
}

// ---------------- embedding gather ------------------------------------------
__global__ void embed_kernel(const int* __restrict__ tok,
                             const float* __restrict__ emb,
                             float* __restrict__ x) {
    const int s = blockIdx.x, d = threadIdx.x;
    x[s * H + d] = emb[(long)tok[s] * H + d];
}

// ---------------- generic 128x128x8 SGEMM (NN or NT) -------------------------
// C[z][m][n] = scale * sum_k A[z][m][k] * (TRANSB ? B[z][n][k] : B[z][k][n])
//              (+ bias[z][n]) (+ resid[m][n])
template <bool TRANSB>
__global__ void __launch_bounds__(256)
sgemm_kernel(const float* __restrict__ A, const float* __restrict__ B,
             float* __restrict__ C,
             int M, int N, int K,
             long sA, long sB, long sC, int ldc,
             const float* __restrict__ bias, int sBias,
             const float* __restrict__ resid, float scale) {
    __shared__ float As[8][132];
    __shared__ float Bs[8][132];
    const int z = blockIdx.z;
    A += (long)z * sA;
    B += (long)z * sB;
    float* Cz = C + (long)z * sC;
    const int m0 = blockIdx.y * 128;
    const int n0 = blockIdx.x * 128;
    const int tid = threadIdx.x;
    const int arow = tid >> 1, ac4 = (tid & 1) * 4;
    const int ty = tid >> 4, tx = tid & 15;

    float acc[8][8];
#pragma unroll
    for (int i = 0; i < 8; i++)
#pragma unroll
        for (int j = 0; j < 8; j++) acc[i][j] = 0.f;

    for (int k0 = 0; k0 < K; k0 += 8) {
        float4 av = *(const float4*)&A[(long)(m0 + arow) * K + k0 + ac4];
        As[ac4 + 0][arow] = av.x;
        As[ac4 + 1][arow] = av.y;
        As[ac4 + 2][arow] = av.z;
        As[ac4 + 3][arow] = av.w;
        if (!TRANSB) {
            const int br = tid >> 5, bc4 = (tid & 31) * 4;
            float4 bv = *(const float4*)&B[(long)(k0 + br) * N + n0 + bc4];
            *(float4*)&Bs[br][bc4] = bv;
        } else {
            const int bn = tid >> 1, bk4 = (tid & 1) * 4;
            float4 bv = *(const float4*)&B[(long)(n0 + bn) * K + k0 + bk4];
            Bs[bk4 + 0][bn] = bv.x;
            Bs[bk4 + 1][bn] = bv.y;
            Bs[bk4 + 2][bn] = bv.z;
            Bs[bk4 + 3][bn] = bv.w;
        }
        __syncthreads();
#pragma unroll
        for (int k = 0; k < 8; k++) {
            float a[8], b[8];
            *(float4*)&a[0] = *(const float4*)&As[k][ty * 8];
            *(float4*)&a[4] = *(const float4*)&As[k][ty * 8 + 4];
            *(float4*)&b[0] = *(const float4*)&Bs[k][tx * 8];
            *(float4*)&b[4] = *(const float4*)&Bs[k][tx * 8 + 4];
#pragma unroll
            for (int i = 0; i < 8; i++)
#pragma unroll
                for (int j = 0; j < 8; j++) acc[i][j] += a[i] * b[j];
        }
        __syncthreads();
    }
#pragma unroll
    for (int i = 0; i < 8; i++) {
        const int m = m0 + ty * 8 + i;
#pragma unroll
        for (int j = 0; j < 8; j++) {
            const int n = n0 + tx * 8 + j;
            float v = acc[i][j] * scale;
            if (bias)  v += bias[(long)sBias * z + n];
            if (resid) v += resid[(long)m * N + n];
            Cz[(long)m * ldc + n] = v;
        }
    }
}

// ---------------- row softmax over 4096 (grid: (S, NH), 256 thr) -------------
__global__ void softmax_kernel(float* __restrict__ att) {
    float* p = att + ((long)blockIdx.y * S + blockIdx.x) * S;
    const int tid = threadIdx.x;
    __shared__ float red[8];
    float v[16];
    float mx = -3.4e38f;
#pragma unroll
    for (int r = 0; r < 16; r++) {
        v[r] = p[r * 256 + tid];
        mx = fmaxf(mx, v[r]);
    }
#pragma unroll
    for (int o = 16; o > 0; o >>= 1) mx = fmaxf(mx, __shfl_xor_sync(~0u, mx, o));
    if ((tid & 31) == 0) red[tid >> 5] = mx;
    __syncthreads();
    mx = red[0];
#pragma unroll
    for (int w = 1; w < 8; w++) mx = fmaxf(mx, red[w]);
    __syncthreads();

    float sum = 0.f;
#pragma unroll
    for (int r = 0; r < 16; r++) {
        v[r] = expf(v[r] - mx);
        sum += v[r];
    }
#pragma unroll
    for (int o = 16; o > 0; o >>= 1) sum += __shfl_xor_sync(~0u, sum, o);
    if ((tid & 31) == 0) red[tid >> 5] = sum;
    __syncthreads();
    sum = 0.f;
#pragma unroll
    for (int w = 0; w < 8; w++) sum += red[w];
    const float inv = 1.f / sum;
#pragma unroll
    for (int r = 0; r < 16; r++) p[r * 256 + tid] = v[r] * inv;
}

// ---------------- LayerNorm (grid: S, 256 thr, one element/thread) -----------
__global__ void ln_kernel(const float* __restrict__ pre,
                          const float* __restrict__ g,
                          const float* __restrict__ b,
                          float* __restrict__ y) {
    const int s = blockIdx.x, tid = threadIdx.x;
    __shared__ float red[8];
    float v = pre[s * H + tid];
    float sum = v;
#pragma unroll
    for (int o = 16; o > 0; o >>= 1) sum += __shfl_xor_sync(~0u, sum, o);
    if ((tid & 31) == 0) red[tid >> 5] = sum;
    __syncthreads();
    sum = 0.f;
#pragma unroll
    for (int w = 0; w < 8; w++) sum += red[w];
    const float mu = sum * (1.f / H);
    const float d = v - mu;
    __syncthreads();
    float s2 = d * d;
#pragma unroll
    for (int o = 16; o > 0; o >>= 1) s2 += __shfl_xor_sync(~0u, s2, o);
    if ((tid & 31) == 0) red[tid >> 5] = s2;
    __syncthreads();
    s2 = 0.f;
#pragma unroll
    for (int w = 0; w < 8; w++) s2 += red[w];
    const float var = s2 * (1.f / H);
    y[s * H + tid] = d * rsqrtf(var + LN_EPS) * g[tid] + b[tid];
}

// ---------------- GRU scan: 8-CTA cluster, W_hh in registers -----------------
// CTA c owns hidden indices [c*32, c*32+32). 768 threads: 96 rows x 8 lanes.
// Per step: reg-matvec vs smem h -> shfl reduce -> 32 threads do gates ->
// DSMEM-broadcast new h slice to all 8 CTAs -> cluster barrier. Double-buffered h.
__global__ void __cluster_dims__(8, 1, 1) __launch_bounds__(768, 1)
gru_kernel(const float* __restrict__ gi, const float* __restrict__ Whh,
           const float* __restrict__ bhh, float* __restrict__ out, int out_size) {
    __shared__ float h_s[2][H];
    __shared__ float gh_s[96];
    const int tid = threadIdx.x;
    const int cta = blockIdx.x;
    const int lr = tid >> 3, sub = tid & 7;   // local row 0..95, lane-in-row
    const int gate = lr >> 5;                 // 0:r 1:z 2:n
    const int iloc = lr & 31;
    const int grow = gate * H + cta * 32 + iloc;

    float w[32];
#pragma unroll
    for (int k = 0; k < 32; k++) w[k] = Whh[grow * H + sub + 8 * k];

    if (tid < H) h_s[0][tid] = 0.f;

    float bhr = 0.f, bhz = 0.f, bhn = 0.f;
    int gidx = 0;
    if (tid < 32) {
        gidx = cta * 32 + tid;
        bhr = bhh[gidx];
        bhz = bhh[H + gidx];
        bhn = bhh[2 * H + gidx];
    }
    const uint32_t h0a = smem_u32(&h_s[0][0]);
    const uint32_t h1a = smem_u32(&h_s[1][0]);
    cluster_sync_();

    for (int t = 0; t < S; t++) {
        const float* hb = h_s[t & 1];
        float ir = 0.f, iz = 0.f, in_ = 0.f;
        if (tid < 32) {   // prefetch input gates (latency hidden by matvec)
            const long base = (long)t * TH + gidx;
            ir = gi[base];
            iz = gi[base + H];
            in_ = gi[base + 2 * H];
        }
        float acc = 0.f;
#pragma unroll
        for (int k = 0; k < 32; k++) acc += w[k] * hb[sub + 8 * k];
        acc += __shfl_xor_sync(~0u, acc, 4);
        acc += __shfl_xor_sync(~0u, acc, 2);
        acc += __shfl_xor_sync(~0u, acc, 1);
        if (sub == 0) gh_s[lr] = acc;
        __syncthreads();
        if (tid < 32) {
            const float hr = gh_s[tid] + bhr;
            const float hz = gh_s[32 + tid] + bhz;
            const float hn = gh_s[64 + tid] + bhn;
            const float r  = 1.f / (1.f + expf(-(ir + hr)));
            const float zg = 1.f / (1.f + expf(-(iz + hz)));
            const float n  = tanhf(in_ + r * hn);
            const float hnew = (1.f - zg) * n + zg * hb[gidx];
            const uint32_t dst = ((t & 1) ? h0a : h1a) + (uint32_t)gidx * 4u;
#pragma unroll
            for (uint32_t p = 0; p < 8; p++) st_cluster_f32(dst, p, hnew);
        }
        cluster_sync_();
    }
    if (cta == 0 && tid < H) {
        const float hv = h_s[0][tid];   // after t=4095 (odd), final h is in buf 0
        out[tid] = hv;
        if (out_size >= 2 * H) out[H + tid] = hv;
    }
}

// ---------------- host orchestration ----------------------------------------
extern "C" void kernel_launch(void* const* d_in, const int* in_sizes, int n_in,
                              void* d_out, int out_size) {
    const int*   tokens = (const int*)  d_in[0];
    const float* emb    = (const float*)d_in[1];
    const float* Wq     = (const float*)d_in[2];
    const float* bq     = (const float*)d_in[3];
    const float* Wk     = (const float*)d_in[4];
    const float* bk     = (const float*)d_in[5];
    const float* Wv     = (const float*)d_in[6];
    const float* bv     = (const float*)d_in[7];
    const float* Wo     = (const float*)d_in[8];
    const float* bo     = (const float*)d_in[9];
    const float* ln_g   = (const float*)d_in[10];
    const float* ln_b   = (const float*)d_in[11];
    const float* W_ih   = (const float*)d_in[12];
    const float* W_hh   = (const float*)d_in[13];
    const float* b_ih   = (const float*)d_in[14];
    const float* b_hh   = (const float*)d_in[15];
    (void)in_sizes; (void)n_in;

    float *x, *q, *k, *v, *att, *o, *pre, *y, *gi;
    cudaGetSymbolAddress((void**)&x,   g_x);
    cudaGetSymbolAddress((void**)&q,   g_q);
    cudaGetSymbolAddress((void**)&k,   g_k);
    cudaGetSymbolAddress((void**)&v,   g_v);
    cudaGetSymbolAddress((void**)&att, g_att);
    cudaGetSymbolAddress((void**)&o,   g_o);
    cudaGetSymbolAddress((void**)&pre, g_pre);
    cudaGetSymbolAddress((void**)&y,   g_y);
    cudaGetSymbolAddress((void**)&gi,  g_gi);

    embed_kernel<<<S, H>>>(tokens, emb, x);

    // q/k/v: [4096,256] @ [256,256] per head, bias per head
    const dim3 gQKV(2, 32, NH);
    sgemm_kernel<false><<<gQKV, 256>>>(x, Wq, q, S, H, H, 0, (long)H * H,
                                       (long)S * H, H, bq, H, nullptr, 1.f);
    sgemm_kernel<false><<<gQKV, 256>>>(x, Wk, k, S, H, H, 0, (long)H * H,
                                       (long)S * H, H, bk, H, nullptr, 1.f);
    sgemm_kernel<false><<<gQKV, 256>>>(x, Wv, v, S, H, H, 0, (long)H * H,
                                       (long)S * H, H, bv, H, nullptr, 1.f);

    // scores = q @ k^T / sqrt(H)
    sgemm_kernel<true><<<dim3(32, 32, NH), 256>>>(q, k, att, S, S, H,
                                                  (long)S * H, (long)S * H,
                                                  (long)S * S, S,
                                                  nullptr, 0, nullptr, 1.f / 16.f);
    softmax_kernel<<<dim3(S, NH), 256>>>(att);

    // o[s, h*H+e] = att[h] @ v[h]   (ldc = NH*H, per-head column offset)
    sgemm_kernel<false><<<dim3(2, 32, NH), 256>>>(att, v, o, S, H, S,
                                                  (long)S * S, (long)S * H,
                                                  (long)H, NH * H,
                                                  nullptr, 0, nullptr, 1.f);

    // pre = x + o @ Wo + bo
    sgemm_kernel<false><<<dim3(2, 32, 1), 256>>>(o, Wo, pre, S, H, NH * H,
                                                 0, 0, 0, H, bo, 0, x, 1.f);
    ln_kernel<<<S, H>>>(pre, ln_g, ln_b, y);

    // gi = y @ W_ih^T + b_ih
    sgemm_kernel<true><<<dim3(6, 32, 1), 256>>>(y, W_ih, gi, S, TH, H,
                                                0, 0, 0, TH, b_ih, 0, nullptr, 1.f);

    gru_kernel<<<8, 768>>>(gi, W_hh, b_hh, (float*)d_out, out_size);
}